// round 1
// baseline (speedup 1.0000x reference)
#include <cuda_runtime.h>
#include <cstdint>
#include <cstddef>

#define B_ 512
#define K_ 128
#define D_ 512

// Scratch (static device globals — no allocation in kernel_launch).
__device__ float  g_cost[(size_t)B_ * K_ * K_];   // 32 MB
__device__ int    g_perm[B_ * K_];                // row -> matched column
__device__ double g_part[B_];                     // per-batch loss partial

// ---------------------------------------------------------------------------
// Kernel 1: per-batch cost matrix  C = ||x||^2 + ||y||^2 - 2 X Y^T
// One block per batch, 256 threads, 8x8 register tile per thread.
// ---------------------------------------------------------------------------
__global__ void __launch_bounds__(256) cost_kernel(const float* __restrict__ X,
                                                   const float* __restrict__ Y)
{
    int b = blockIdx.x;
    const float* x = X + (size_t)b * K_ * D_;
    const float* y = Y + (size_t)b * K_ * D_;
    float* cb = g_cost + (size_t)b * K_ * K_;

    __shared__ float xs[32][132];   // [k][i], padded
    __shared__ float ys[32][132];   // [k][j], padded
    __shared__ float sn[2][128];    // row norms of x (0) and y (1)

    int tid = threadIdx.x;

    // Row squared norms: threads 0..127 -> x rows, 128..255 -> y rows.
    {
        const float* src = (tid < 128) ? x : y;
        int r = tid & 127;
        const float4* p4 = reinterpret_cast<const float4*>(src + (size_t)r * D_);
        float s = 0.f;
        #pragma unroll 8
        for (int k = 0; k < D_ / 4; ++k) {
            float4 v = p4[k];
            s += v.x * v.x + v.y * v.y + v.z * v.z + v.w * v.w;
        }
        sn[tid >> 7][r] = s;
    }

    float acc[8][8];
    #pragma unroll
    for (int a = 0; a < 8; ++a)
        #pragma unroll
        for (int c = 0; c < 8; ++c) acc[a][c] = 0.f;

    int ti = tid >> 4;      // 0..15 -> rows ti*8..ti*8+7
    int tj = tid & 15;      // 0..15 -> cols tj*8..tj*8+7

    for (int k0 = 0; k0 < D_; k0 += 32) {
        __syncthreads();
        // Load 128x32 tiles of X and Y, transposed into [k][row].
        #pragma unroll
        for (int l = 0; l < 4; ++l) {
            int f = tid + l * 256;          // 0..1023
            int row = f >> 3;               // 0..127
            int c = f & 7;                  // float4 index along k
            float4 vx = *reinterpret_cast<const float4*>(x + (size_t)row * D_ + k0 + c * 4);
            float4 vy = *reinterpret_cast<const float4*>(y + (size_t)row * D_ + k0 + c * 4);
            int kk = c * 4;
            xs[kk + 0][row] = vx.x; xs[kk + 1][row] = vx.y;
            xs[kk + 2][row] = vx.z; xs[kk + 3][row] = vx.w;
            ys[kk + 0][row] = vy.x; ys[kk + 1][row] = vy.y;
            ys[kk + 2][row] = vy.z; ys[kk + 3][row] = vy.w;
        }
        __syncthreads();
        #pragma unroll 4
        for (int k = 0; k < 32; ++k) {
            float4 t0 = *reinterpret_cast<const float4*>(&xs[k][ti * 8]);
            float4 t1 = *reinterpret_cast<const float4*>(&xs[k][ti * 8 + 4]);
            float4 t2 = *reinterpret_cast<const float4*>(&ys[k][tj * 8]);
            float4 t3 = *reinterpret_cast<const float4*>(&ys[k][tj * 8 + 4]);
            float a[8]  = {t0.x, t0.y, t0.z, t0.w, t1.x, t1.y, t1.z, t1.w};
            float bb[8] = {t2.x, t2.y, t2.z, t2.w, t3.x, t3.y, t3.z, t3.w};
            #pragma unroll
            for (int ii = 0; ii < 8; ++ii)
                #pragma unroll
                for (int jj = 0; jj < 8; ++jj)
                    acc[ii][jj] = fmaf(a[ii], bb[jj], acc[ii][jj]);
        }
    }

    // Write out: c[i][j] = sn_x[i] + sn_y[j] - 2*dot
    #pragma unroll
    for (int ii = 0; ii < 8; ++ii) {
        int i = ti * 8 + ii;
        float sxi = sn[0][i];
        int jb = tj * 8;
        float4 o0, o1;
        o0.x = sxi + sn[1][jb + 0] - 2.f * acc[ii][0];
        o0.y = sxi + sn[1][jb + 1] - 2.f * acc[ii][1];
        o0.z = sxi + sn[1][jb + 2] - 2.f * acc[ii][2];
        o0.w = sxi + sn[1][jb + 3] - 2.f * acc[ii][3];
        o1.x = sxi + sn[1][jb + 4] - 2.f * acc[ii][4];
        o1.y = sxi + sn[1][jb + 5] - 2.f * acc[ii][5];
        o1.z = sxi + sn[1][jb + 6] - 2.f * acc[ii][6];
        o1.w = sxi + sn[1][jb + 7] - 2.f * acc[ii][7];
        *reinterpret_cast<float4*>(&cb[(size_t)i * K_ + jb])     = o0;
        *reinterpret_cast<float4*>(&cb[(size_t)i * K_ + jb + 4]) = o1;
    }
}

// ---------------------------------------------------------------------------
// Kernel 2: Jonker-Volgenant LAP, one block (128 threads) per batch.
// Thread t owns column j = t+1. v, minv, used live in registers.
// ---------------------------------------------------------------------------
__device__ __forceinline__ unsigned int fenc(float f)
{
    unsigned int u = __float_as_uint(f);
    return (u & 0x80000000u) ? ~u : (u | 0x80000000u);
}
__device__ __forceinline__ float fdec(unsigned int u)
{
    unsigned int bits = (u & 0x80000000u) ? (u ^ 0x80000000u) : ~u;
    return __uint_as_float(bits);
}

__global__ void __launch_bounds__(128) hungarian_kernel()
{
    extern __shared__ float cost_s[];       // K_*K_ floats (64 KB)
    __shared__ float u_s[K_ + 1];
    __shared__ int   p_s[K_ + 1];           // p[j] = row matched to column j
    __shared__ int   way_s[K_ + 1];
    __shared__ unsigned int s_wk[4];
    __shared__ int   s_wj[4];
    __shared__ float s_delta;
    __shared__ int   s_j0, s_j1;

    int b = blockIdx.x;
    int t = threadIdx.x;
    int lane = t & 31, w = t >> 5;

    // Stage cost matrix into shared memory (vectorized, coalesced).
    {
        const float4* src = reinterpret_cast<const float4*>(g_cost + (size_t)b * K_ * K_);
        float4* dst = reinterpret_cast<float4*>(cost_s);
        #pragma unroll
        for (int q = 0; q < (K_ * K_ / 4) / 128; ++q)
            dst[t + q * 128] = src[t + q * 128];
    }
    u_s[t + 1] = 0.f;
    p_s[t + 1] = 0;
    if (t == 0) { u_s[0] = 0.f; p_s[0] = 0; }

    const int j = t + 1;     // this thread's column
    float vj = 0.f;          // v[j]
    __syncthreads();

    for (int i = 1; i <= K_; ++i) {
        if (t == 0) { p_s[0] = i; s_j0 = 0; }
        float minvj = 3.0e38f;
        bool usedj = false;
        __syncthreads();

        while (true) {
            int j0 = s_j0;
            if (j == j0) usedj = true;      // used[j0] = true
            int i0 = p_s[j0];
            float ui0 = u_s[i0];
            if (!usedj) {
                float cur = cost_s[(size_t)(i0 - 1) * K_ + t] - ui0 - vj;
                if (cur < minvj) { minvj = cur; way_s[j] = j0; }
            }
            // argmin over free columns: order-preserving u32 encoding + redux.
            unsigned int key = usedj ? 0xFFFFFFFFu : fenc(minvj);
            unsigned int m   = __reduce_min_sync(0xFFFFFFFFu, key);
            unsigned int bal = __ballot_sync(0xFFFFFFFFu, key == m);
            if (lane == 0) { s_wk[w] = m; s_wj[w] = (w << 5) + __ffs(bal); }  // column index
            __syncthreads();
            if (t == 0) {
                unsigned int mk = s_wk[0]; int mj = s_wj[0];
                #pragma unroll
                for (int q = 1; q < 4; ++q)
                    if (s_wk[q] < mk) { mk = s_wk[q]; mj = s_wj[q]; }
                s_delta = fdec(mk);
                s_j1 = mj;
                s_j0 = mj;
            }
            __syncthreads();
            float delta = s_delta;
            int j1 = s_j1;
            if (usedj) { u_s[p_s[j]] += delta; vj -= delta; }  // distinct rows: no conflict
            else       { minvj -= delta; }
            if (t == 0) u_s[i] += delta;                       // virtual column 0 (p[0]=i)
            bool done = (p_s[j1] == 0);
            __syncthreads();
            if (done) break;
        }
        // Augment along alternating path (serial, tiny).
        if (t == 0) {
            int j0 = s_j0;
            while (j0 != 0) { int jp = way_s[j0]; p_s[j0] = p_s[jp]; j0 = jp; }
        }
        __syncthreads();
    }
    // col_ind[p[j]-1] = j-1
    g_perm[b * K_ + (p_s[j] - 1)] = t;
}

// ---------------------------------------------------------------------------
// Kernel 3: exact MSE partials per batch (fp32 diffs like reference, fp64 sum)
// ---------------------------------------------------------------------------
__global__ void __launch_bounds__(256) loss_kernel(const float* __restrict__ X,
                                                   const float* __restrict__ Y)
{
    int b = blockIdx.x;
    int tid = threadIdx.x, lane = tid & 31, w = tid >> 5;
    const float* x = X + (size_t)b * K_ * D_;
    const float* y = Y + (size_t)b * K_ * D_;

    float s = 0.f;
    for (int i = w; i < K_; i += 8) {
        int c = g_perm[b * K_ + i];
        const float4* xp = reinterpret_cast<const float4*>(x + (size_t)i * D_);
        const float4* yp = reinterpret_cast<const float4*>(y + (size_t)c * D_);
        #pragma unroll
        for (int q = 0; q < 4; ++q) {
            float4 a  = xp[lane + q * 32];
            float4 bb = yp[lane + q * 32];
            float dx = a.x - bb.x, dy = a.y - bb.y;
            float dz = a.z - bb.z, dw = a.w - bb.w;
            s += dx * dx + dy * dy + dz * dz + dw * dw;
        }
    }
    double ds = (double)s;
    #pragma unroll
    for (int off = 16; off; off >>= 1)
        ds += __shfl_down_sync(0xFFFFFFFFu, ds, off);
    __shared__ double wsum[8];
    if (lane == 0) wsum[w] = ds;
    __syncthreads();
    if (tid == 0) {
        double tot = 0.0;
        #pragma unroll
        for (int q = 0; q < 8; ++q) tot += wsum[q];
        g_part[b] = tot;
    }
}

__global__ void __launch_bounds__(512) final_kernel(float* __restrict__ out)
{
    __shared__ double s[512];
    int t = threadIdx.x;
    s[t] = g_part[t];
    __syncthreads();
    for (int stride = 256; stride; stride >>= 1) {
        if (t < stride) s[t] += s[t + stride];
        __syncthreads();
    }
    if (t == 0) out[0] = (float)(s[0] / ((double)B_ * K_ * D_));
}

// ---------------------------------------------------------------------------
extern "C" void kernel_launch(void* const* d_in, const int* in_sizes, int n_in,
                              void* d_out, int out_size)
{
    (void)in_sizes; (void)n_in; (void)out_size;
    const float* X = (const float*)d_in[0];
    const float* Y = (const float*)d_in[1];
    float* out = (float*)d_out;

    cudaFuncSetAttribute(hungarian_kernel,
                         cudaFuncAttributeMaxDynamicSharedMemorySize,
                         K_ * K_ * (int)sizeof(float));

    cost_kernel<<<B_, 256>>>(X, Y);
    hungarian_kernel<<<B_, 128, K_ * K_ * sizeof(float)>>>();
    loss_kernel<<<B_, 256>>>(X, Y);
    final_kernel<<<1, 512>>>(out);
}